// round 10
// baseline (speedup 1.0000x reference)
#include <cuda_runtime.h>
#include <cuda_fp16.h>
#include <cstdint>

#define MDIM 81984   // B*V
#define VV   2562
#define HH   192
#define BB   32
#define KP_H 96      // k-pairs for K=192
#define KP_1 496     // k-pairs for layer1 (K=966 padded to 992, even # of k16 tiles)
#define NT_H 12
#define NT_1 62
#define WROWS (KP_1 + 12 * KP_H)

// ---------------- scratch (device globals) ----------------------------------
static __device__ uint32_t g_Sp[(size_t)MDIM * KP_H];   // GEMM out, half2 pairs (side pre-scaled)
static __device__ uint32_t g_Xp [(size_t)MDIM * KP_H];  // X fp16 pairs
static __device__ uint32_t g_Fp [(size_t)MDIM * KP_H];  // feats fp16 pairs (the only feats copy)
static __device__ uint32_t g_A1p[(size_t)MDIM * KP_1];  // layer1 concat fp16 pairs
static __device__ uint32_t g_W  [(size_t)WROWS * HH];   // weight fp16 pairs [kpair][n]
static __device__ float    g_S3[(size_t)MDIM * 3];
static __device__ int      g_nbr[VV * 8];
static __device__ float    g_w [VV * 8];
static __device__ int      g_cnt[VV];
static __device__ float    g_invdeg[VV];

// ---------------- helpers ----------------------------------------------------
__device__ __forceinline__ uint32_t packh2(float x0, float x1) {
    __half2 h = __floats2half2_rn(x0, x1);
    return *reinterpret_cast<uint32_t*>(&h);
}
__device__ __forceinline__ float2 unpackh2(uint32_t u) {
    __half2 h = *reinterpret_cast<__half2*>(&u);
    return __half22float2(h);
}

__device__ __forceinline__ void mma16(float* c, const uint32_t* a, const uint32_t* b) {
    asm volatile(
        "mma.sync.aligned.m16n8k16.row.col.f32.f16.f16.f32 "
        "{%0,%1,%2,%3}, {%4,%5,%6,%7}, {%8,%9}, {%0,%1,%2,%3};\n"
        : "+f"(c[0]), "+f"(c[1]), "+f"(c[2]), "+f"(c[3])
        : "r"(a[0]), "r"(a[1]), "r"(a[2]), "r"(a[3]), "r"(b[0]), "r"(b[1]));
}

__device__ __forceinline__ void ldsm4(uint32_t* r, uint32_t addr) {
    asm volatile("ldmatrix.sync.aligned.m8n8.x4.shared.b16 {%0,%1,%2,%3}, [%4];\n"
        : "=r"(r[0]), "=r"(r[1]), "=r"(r[2]), "=r"(r[3]) : "r"(addr));
}

__device__ __forceinline__ uint32_t smem_u32(const void* p) {
    return (uint32_t)__cvta_generic_to_shared(p);
}
__device__ __forceinline__ void cpa16(uint32_t dst, const void* src, int sz) {
    asm volatile("cp.async.cg.shared.global [%0], [%1], 16, %2;\n"
                 :: "r"(dst), "l"(src), "r"(sz));
}

// ---------------- adjacency extraction ---------------------------------------
__global__ __launch_bounds__(256) void adj_kernel(const float* __restrict__ adj) {
    int u = blockIdx.x * (blockDim.x / 32) + (threadIdx.x / 32);
    int lane = threadIdx.x & 31;
    if (u >= VV) return;
    int cnt = 0;
    float deg = 0.f;
    for (int base = 0; base < VV; base += 32) {
        int v = base + lane;
        float f = (v < VV) ? adj[(size_t)u * VV + v] : 0.f;
        unsigned mask = __ballot_sync(0xffffffffu, f != 0.f);
        deg += f;
        if (f != 0.f) {
            int pos = cnt + __popc(mask & ((1u << lane) - 1u));
            if (pos < 8) { g_nbr[u * 8 + pos] = v; g_w[u * 8 + pos] = f; }
        }
        cnt += __popc(mask);
    }
    #pragma unroll
    for (int o = 16; o > 0; o >>= 1) deg += __shfl_down_sync(0xffffffffu, deg, o);
    if (lane == 0) {
        g_cnt[u] = cnt < 8 ? cnt : 8;
        g_invdeg[u] = 1.f / deg;
    }
}

// ---------------- weight pack (single fp16 plane): W1 + Wm -------------------
__global__ __launch_bounds__(256) void prep_w_kernel(const float* __restrict__ W1,
                                                     const float* __restrict__ Wm) {
    int idx = blockIdx.x * 256 + threadIdx.x;
    if (idx >= WROWS * HH) return;
    int kp = idx / HH, n = idx % HH;
    float x0, x1;
    if (kp < KP_1) {
        int k = 2 * kp;
        x0 = (k < 966)     ? W1[(size_t)k * HH + n]       : 0.f;
        x1 = (k + 1 < 966) ? W1[(size_t)(k + 1) * HH + n] : 0.f;
    } else {
        int r = kp - KP_1;
        int mat = r / KP_H, kpp = r % KP_H;
        int k = 2 * kpp;
        const float* Wb = Wm + (size_t)mat * HH * HH;
        x0 = Wb[(size_t)k * HH + n];
        x1 = Wb[(size_t)(k + 1) * HH + n];
    }
    g_W[idx] = packh2(x0, x1);
}

// ---------------- layer1 input pack: concat(F3,P) -> g_A1p --------------------
__global__ __launch_bounds__(256) void prep_a1_kernel(const float* __restrict__ F3,
                                                      const float* __restrict__ P) {
    size_t idx = (size_t)blockIdx.x * 256 + threadIdx.x;
    if (idx >= (size_t)MDIM * KP_1) return;
    int m = (int)(idx / KP_1), kp = (int)(idx % KP_1);
    int c = 2 * kp;
    float x0 = 0.f, x1 = 0.f;
    if (c < 3)        x0 = F3[m * 3 + c];
    else if (c < 966) x0 = P[(size_t)m * 963 + (c - 3)];
    int c1 = c + 1;
    if (c1 < 3)        x1 = F3[m * 3 + c1];
    else if (c1 < 966) x1 = P[(size_t)m * 963 + (c1 - 3)];
    g_A1p[idx] = packh2(x0, x1);
}

// ---------------- fp16 tensor-core GEMM: g_Sp = A[M,K] @ W[K,192] -------------
// block tile 256x64, warp tile 64x32 (4mt x 4nt), 4-stage cp.async pipeline,
// TWO k-tiles per sync window. A fragments via ldmatrix.x4.
// epilogue: cols < 64 scaled by invdeg[row % V]
// asel: 0 -> g_Xp (akp=96), 1 -> g_Fp (96), 2 -> g_A1p (496)
__global__ __launch_bounds__(256, 2) void gemm_f16_kernel(int asel, int woff, int NT) {
    __shared__ uint32_t As[4][256][8];      // swizzled: col ^= ((row>>2)&1)*4
    __shared__ uint32_t Bs[4][8][72];       // [stage][kpair][n], padded

    const uint32_t* Ap; int akp;
    if (asel == 0)      { Ap = g_Xp;  akp = KP_H; }
    else if (asel == 1) { Ap = g_Fp;  akp = KP_H; }
    else                { Ap = g_A1p; akp = KP_1; }

    int t = threadIdx.x, lane = t & 31, warp = t >> 5;
    int wm = (warp >> 1) * 64, wn = (warp & 1) * 32;
    int g = lane >> 2, t4 = lane & 3;
    int rowBase = blockIdx.y * 256, colBase = blockIdx.x * 64;

    float acc[4][4][4];
    #pragma unroll
    for (int mt = 0; mt < 4; mt++)
        #pragma unroll
        for (int nt = 0; nt < 4; nt++)
            #pragma unroll
            for (int i = 0; i < 4; i++) acc[mt][nt][i] = 0.f;

    int b_kp = t >> 4, b_n4 = (t & 15) * 4;
    int lm_row = lane & 15;
    int lm_k4  = (lane >> 4) * 4;

    auto load_stage = [&](int kt) {
        int s = kt & 3;
        int k0p = kt * 8;
        int ok = (kt < NT) ? 16 : 0;
        #pragma unroll
        for (int i = 0; i < 2; i++) {
            int c = t + i * 256;
            int row = c >> 1, half = c & 1;
            int gm = rowBase + row;
            int dcol = (half * 4) ^ (((row >> 2) & 1) * 4);
            cpa16(smem_u32(&As[s][row][dcol]),
                  Ap + (size_t)gm * akp + k0p + half * 4,
                  (gm < MDIM) ? ok : 0);
        }
        if (t < 128)
            cpa16(smem_u32(&Bs[s][b_kp][b_n4]),
                  g_W + (size_t)(woff + k0p + b_kp) * HH + colBase + b_n4,
                  ok);
        asm volatile("cp.async.commit_group;\n");
    };

    auto compute_tile = [&](int kt) {
        int s = kt & 3;
        uint32_t a[4][4];
        #pragma unroll
        for (int mt = 0; mt < 4; mt++) {
            int row = wm + mt * 16 + lm_row;
            int col = lm_k4 ^ (((row >> 2) & 1) * 4);
            ldsm4(a[mt], smem_u32(&As[s][row][col]));
        }
        #pragma unroll
        for (int nt = 0; nt < 4; nt++) {
            int cn = wn + nt * 8 + g;
            uint32_t b[2] = { Bs[s][t4][cn], Bs[s][t4 + 4][cn] };
            #pragma unroll
            for (int mt = 0; mt < 4; mt++)
                mma16(acc[mt][nt], a[mt], b);
        }
    };

    load_stage(0);
    load_stage(1);
    load_stage(2);

    for (int kt = 0; kt < NT; kt += 2) {
        asm volatile("cp.async.wait_group %0;\n" :: "n"(1));
        __syncthreads();
        compute_tile(kt);
        compute_tile(kt + 1);
        __syncthreads();
        load_stage(kt + 3);
        load_stage(kt + 4);
    }

    // ---- epilogue: pack half2, scale side channels ----
    #pragma unroll
    for (int mt = 0; mt < 4; mt++) {
        int gm0 = rowBase + wm + mt * 16 + g;
        #pragma unroll
        for (int nt = 0; nt < 4; nt++) {
            int gc = colBase + wn + nt * 8 + t4 * 2;
            int cp = gc >> 1;
            bool side = (gc < 64);
            if (gm0 < MDIM) {
                float sc = side ? g_invdeg[gm0 % VV] : 1.f;
                g_Sp[(size_t)gm0 * KP_H + cp] = packh2(acc[mt][nt][0] * sc, acc[mt][nt][1] * sc);
            }
            int gm1 = gm0 + 8;
            if (gm1 < MDIM) {
                float sc = side ? g_invdeg[gm1 % VV] : 1.f;
                g_Sp[(size_t)gm1 * KP_H + cp] = packh2(acc[mt][nt][2] * sc, acc[mt][nt][3] * sc);
            }
        }
    }
}

// ---------------- fused combine + BN stats + apply (per vertex) --------------
// mode 0: X = relu(bn)                (write g_Xp plane)
// mode 1: F = (concat_first192+y)/2   (write g_Fp)
// mode 2: F = (F + y)/2               (g_Fp read+write)
// mode 3: mode 2 + write dout (fp32 value before fp16 rounding)
__global__ __launch_bounds__(256) void post_kernel(
    const float* __restrict__ bias,
    const float* __restrict__ gam, const float* __restrict__ bet,
    const float* __restrict__ F3, const float* __restrict__ P,
    float* __restrict__ dout, int mode)
{
    int v = blockIdx.x, t = threadIdx.x;
    __shared__ float ybuf[BB * HH];
    __shared__ float sbias[HH];
    __shared__ int   s_nbr[8];
    __shared__ float s_w[8];
    __shared__ int   s_cnt;
    __shared__ float redS[8], redQ[8];
    __shared__ float s_mean, s_istd;

    if (t < 8) { s_nbr[t] = g_nbr[v * 8 + t]; s_w[t] = g_w[v * 8 + t]; }
    if (t == 0) s_cnt = g_cnt[v];
    if (t < HH) sbias[t] = bias[t];
    __syncthreads();
    int cnt = s_cnt;

    float s = 0.f, ss = 0.f;
    #pragma unroll
    for (int it = 0; it < 12; it++) {
        int i = t + it * 256;
        int b = i / KP_H, cp = i - b * KP_H;
        int c = 2 * cp;
        float y0, y1;
        if (cp < 64) {
            float2 p = unpackh2(g_Sp[((size_t)(b * VV + v)) * KP_H + cp + 32]);
            y0 = p.x; y1 = p.y;
        } else {
            int dp = cp - 64;
            y0 = 0.f; y1 = 0.f;
            for (int j = 0; j < cnt; j++) {
                float2 p = unpackh2(g_Sp[((size_t)(b * VV + s_nbr[j])) * KP_H + dp]);
                y0 += s_w[j] * p.x; y1 += s_w[j] * p.y;
            }
        }
        y0 += sbias[c]; y1 += sbias[c + 1];
        ybuf[2 * i] = y0; ybuf[2 * i + 1] = y1;
        s += y0 + y1; ss += y0 * y0 + y1 * y1;
    }
    #pragma unroll
    for (int o = 16; o > 0; o >>= 1) {
        s  += __shfl_down_sync(0xffffffffu, s, o);
        ss += __shfl_down_sync(0xffffffffu, ss, o);
    }
    int lane = t & 31, warp = t >> 5;
    if (lane == 0) { redS[warp] = s; redQ[warp] = ss; }
    __syncthreads();
    if (t == 0) {
        float S = 0.f, Q = 0.f;
        #pragma unroll
        for (int w = 0; w < 8; w++) { S += redS[w]; Q += redQ[w]; }
        float n = (float)(BB * HH);
        float mu = S / n;
        s_mean = mu;
        s_istd = rsqrtf(Q / n - mu * mu + 1e-5f);
    }
    __syncthreads();

    float gv = gam[v], bv = bet[v], mu = s_mean, istd = s_istd;
    #pragma unroll
    for (int it = 0; it < 12; it++) {
        int i = t + it * 256;
        int b = i / KP_H, cp = i - b * KP_H;
        int c = 2 * cp;
        int m = b * VV + v;
        float y0 = fmaxf(gv * (ybuf[2 * i]     - mu) * istd + bv, 0.f);
        float y1 = fmaxf(gv * (ybuf[2 * i + 1] - mu) * istd + bv, 0.f);
        size_t pidx = (size_t)m * KP_H + cp;
        if (mode == 0) {
            g_Xp[pidx] = packh2(y0, y1);
        } else {
            float r0, r1;
            if (mode == 1) {
                float b0 = (c < 3)     ? F3[m * 3 + c]     : P[(size_t)m * 963 + (c - 3)];
                float b1 = (c + 1 < 3) ? F3[m * 3 + c + 1] : P[(size_t)m * 963 + (c - 2)];
                r0 = (b0 + y0) * 0.5f; r1 = (b1 + y1) * 0.5f;
            } else {
                float2 f = unpackh2(g_Fp[pidx]);
                r0 = (f.x + y0) * 0.5f; r1 = (f.y + y1) * 0.5f;
            }
            g_Fp[pidx] = packh2(r0, r1);
            if (mode == 3)
                *reinterpret_cast<float2*>(&dout[(size_t)m * HH + c]) = make_float2(r0, r1);
        }
    }
}

// ---------------- head GEMM: S3 = feats @ W15, cols<2 pre-scaled -------------
__global__ __launch_bounds__(256) void gemm3_kernel(const float* __restrict__ W15) {
    int warp = (blockIdx.x * blockDim.x + threadIdx.x) >> 5;
    int lane = threadIdx.x & 31;
    if (warp >= MDIM) return;
    const uint32_t* row = g_Fp + (size_t)warp * KP_H;
    float a0 = 0.f, a1 = 0.f, a2 = 0.f;
    for (int kp = lane; kp < KP_H; kp += 32) {
        float2 f = unpackh2(row[kp]);
        int k = 2 * kp;
        a0 = fmaf(f.x, W15[k * 3 + 0], a0);
        a1 = fmaf(f.x, W15[k * 3 + 1], a1);
        a2 = fmaf(f.x, W15[k * 3 + 2], a2);
        a0 = fmaf(f.y, W15[k * 3 + 3], a0);
        a1 = fmaf(f.y, W15[k * 3 + 4], a1);
        a2 = fmaf(f.y, W15[k * 3 + 5], a2);
    }
    #pragma unroll
    for (int o = 16; o > 0; o >>= 1) {
        a0 += __shfl_down_sync(0xffffffffu, a0, o);
        a1 += __shfl_down_sync(0xffffffffu, a1, o);
        a2 += __shfl_down_sync(0xffffffffu, a2, o);
    }
    if (lane == 0) {
        float inv = g_invdeg[warp % VV];
        g_S3[warp * 3 + 0] = a0 * inv;
        g_S3[warp * 3 + 1] = a1 * inv;
        g_S3[warp * 3 + 2] = a2;
    }
}

__global__ __launch_bounds__(256) void coords_kernel(float* __restrict__ dout,
                                                     const float* __restrict__ b15) {
    int m = blockIdx.x * blockDim.x + threadIdx.x;
    if (m >= MDIM) return;
    int v = m % VV, b = m / VV;
    float s0 = 0.f, s1 = 0.f;
    int cnt = g_cnt[v];
    for (int j = 0; j < cnt; j++) {
        int nv = g_nbr[v * 8 + j];
        float w = g_w[v * 8 + j];
        const float* p = g_S3 + (size_t)(b * VV + nv) * 3;
        s0 += w * p[0];
        s1 += w * p[1];
    }
    float* o = dout + (size_t)MDIM * HH + (size_t)m * 3;
    o[0] = g_S3[m * 3 + 2] + b15[0];
    o[1] = s0 + b15[1];
    o[2] = s1 + b15[2];
}

// ---------------- driver ----------------------------------------------------
extern "C" void kernel_launch(void* const* d_in, const int* in_sizes, int n_in,
                              void* d_out, int out_size) {
    const float* features = (const float*)d_in[0];
    const float* pooled   = (const float*)d_in[1];
    const float* adj      = (const float*)d_in[2];
    const float* W1       = (const float*)d_in[3];
    const float* b1       = (const float*)d_in[4];
    const float* Wm       = (const float*)d_in[5];
    const float* bm       = (const float*)d_in[6];
    const float* W15      = (const float*)d_in[7];
    const float* b15      = (const float*)d_in[8];
    const float* gamma    = (const float*)d_in[9];
    const float* beta     = (const float*)d_in[10];
    float* dout = (float*)d_out;

    dim3 ggrid(3, (MDIM + 255) / 256);

    adj_kernel<<<(VV + 7) / 8, 256>>>(adj);
    prep_w_kernel<<<(WROWS * HH + 255) / 256, 256>>>(W1, Wm);
    prep_a1_kernel<<<(int)(((size_t)MDIM * KP_1 + 255) / 256), 256>>>(features, pooled);

    // layer 1
    gemm_f16_kernel<<<ggrid, 256>>>(2, 0, NT_1);
    post_kernel<<<VV, 256>>>(b1, gamma + 0 * VV, beta + 0 * VV, features, pooled, dout, 0);

    // layer 2
    gemm_f16_kernel<<<ggrid, 256>>>(0, KP_1 + 0 * KP_H, NT_H);
    post_kernel<<<VV, 256>>>(bm + 0 * HH, gamma + 1 * VV, beta + 1 * VV, features, pooled, dout, 1);

    for (int i = 0; i < 5; i++) {
        int wa = 2 * i + 1, wb = 2 * i + 2;
        gemm_f16_kernel<<<ggrid, 256>>>(1, KP_1 + wa * KP_H, NT_H);
        post_kernel<<<VV, 256>>>(bm + wa * HH, gamma + (2 * i + 2) * VV, beta + (2 * i + 2) * VV,
                                 features, pooled, dout, 0);
        gemm_f16_kernel<<<ggrid, 256>>>(0, KP_1 + wb * KP_H, NT_H);
        post_kernel<<<VV, 256>>>(bm + wb * HH, gamma + (2 * i + 3) * VV, beta + (2 * i + 3) * VV,
                                 features, pooled, dout, 2);
    }

    // layer 13
    gemm_f16_kernel<<<ggrid, 256>>>(1, KP_1 + 11 * KP_H, NT_H);
    post_kernel<<<VV, 256>>>(bm + 11 * HH, gamma + 12 * VV, beta + 12 * VV, features, pooled, dout, 3);

    gemm3_kernel<<<(MDIM * 32 + 255) / 256, 256>>>(W15);
    coords_kernel<<<(MDIM + 255) / 256, 256>>>(dout, b15);
}

// round 11
// speedup vs baseline: 1.0283x; 1.0283x over previous
#include <cuda_runtime.h>
#include <cuda_fp16.h>
#include <cstdint>

#define MDIM 81984   // B*V
#define VV   2562
#define HH   192
#define BB   32
#define KP_H 96      // k-pairs for K=192
#define KP_1 488     // k-pairs for layer1 (K=966 padded to 976)
#define NT_H 12
#define NT_1 61
#define WROWS (KP_1 + 12 * KP_H)

// ---------------- scratch (device globals) ----------------------------------
static __device__ uint32_t g_Sside[(size_t)MDIM * 32];  // GEMM out cols 0..63 (pre-scaled), half2
static __device__ uint32_t g_Ssup [(size_t)MDIM * 64];  // GEMM out cols 64..191, half2
static __device__ uint32_t g_Xp [(size_t)MDIM * KP_H];  // X fp16 pairs
static __device__ uint32_t g_Fp [(size_t)MDIM * KP_H];  // feats fp16 pairs (only feats copy)
static __device__ uint32_t g_A1p[(size_t)MDIM * KP_1];  // layer1 concat fp16 pairs
static __device__ uint32_t g_W  [(size_t)WROWS * HH];   // weight fp16 pairs [kpair][n]
static __device__ float    g_S3[(size_t)MDIM * 3];
static __device__ int      g_nbr[VV * 8];
static __device__ float    g_w [VV * 8];
static __device__ int      g_cnt[VV];
static __device__ float    g_invdeg[VV];

// ---------------- helpers ----------------------------------------------------
__device__ __forceinline__ uint32_t packh2(float x0, float x1) {
    __half2 h = __floats2half2_rn(x0, x1);
    return *reinterpret_cast<uint32_t*>(&h);
}
__device__ __forceinline__ float2 unpackh2(uint32_t u) {
    __half2 h = *reinterpret_cast<__half2*>(&u);
    return __half22float2(h);
}

__device__ __forceinline__ void mma16(float* c, const uint32_t* a, const uint32_t* b) {
    asm volatile(
        "mma.sync.aligned.m16n8k16.row.col.f32.f16.f16.f32 "
        "{%0,%1,%2,%3}, {%4,%5,%6,%7}, {%8,%9}, {%0,%1,%2,%3};\n"
        : "+f"(c[0]), "+f"(c[1]), "+f"(c[2]), "+f"(c[3])
        : "r"(a[0]), "r"(a[1]), "r"(a[2]), "r"(a[3]), "r"(b[0]), "r"(b[1]));
}

__device__ __forceinline__ void ldsm4(uint32_t* r, uint32_t addr) {
    asm volatile("ldmatrix.sync.aligned.m8n8.x4.shared.b16 {%0,%1,%2,%3}, [%4];\n"
        : "=r"(r[0]), "=r"(r[1]), "=r"(r[2]), "=r"(r[3]) : "r"(addr));
}

__device__ __forceinline__ uint32_t smem_u32(const void* p) {
    return (uint32_t)__cvta_generic_to_shared(p);
}
__device__ __forceinline__ void cpa16(uint32_t dst, const void* src, int sz) {
    asm volatile("cp.async.cg.shared.global [%0], [%1], 16, %2;\n"
                 :: "r"(dst), "l"(src), "r"(sz));
}

// ---------------- adjacency extraction ---------------------------------------
__global__ __launch_bounds__(256) void adj_kernel(const float* __restrict__ adj) {
    int u = blockIdx.x * (blockDim.x / 32) + (threadIdx.x / 32);
    int lane = threadIdx.x & 31;
    if (u >= VV) return;
    int cnt = 0;
    float deg = 0.f;
    for (int base = 0; base < VV; base += 32) {
        int v = base + lane;
        float f = (v < VV) ? adj[(size_t)u * VV + v] : 0.f;
        unsigned mask = __ballot_sync(0xffffffffu, f != 0.f);
        deg += f;
        if (f != 0.f) {
            int pos = cnt + __popc(mask & ((1u << lane) - 1u));
            if (pos < 8) { g_nbr[u * 8 + pos] = v; g_w[u * 8 + pos] = f; }
        }
        cnt += __popc(mask);
    }
    #pragma unroll
    for (int o = 16; o > 0; o >>= 1) deg += __shfl_down_sync(0xffffffffu, deg, o);
    if (lane == 0) {
        g_cnt[u] = cnt < 8 ? cnt : 8;
        g_invdeg[u] = 1.f / deg;
    }
}

// ---------------- weight pack (single fp16 plane): W1 + Wm -------------------
__global__ __launch_bounds__(256) void prep_w_kernel(const float* __restrict__ W1,
                                                     const float* __restrict__ Wm) {
    int idx = blockIdx.x * 256 + threadIdx.x;
    if (idx >= WROWS * HH) return;
    int kp = idx / HH, n = idx % HH;
    float x0, x1;
    if (kp < KP_1) {
        int k = 2 * kp;
        x0 = (k < 966)     ? W1[(size_t)k * HH + n]       : 0.f;
        x1 = (k + 1 < 966) ? W1[(size_t)(k + 1) * HH + n] : 0.f;
    } else {
        int r = kp - KP_1;
        int mat = r / KP_H, kpp = r % KP_H;
        int k = 2 * kpp;
        const float* Wb = Wm + (size_t)mat * HH * HH;
        x0 = Wb[(size_t)k * HH + n];
        x1 = Wb[(size_t)(k + 1) * HH + n];
    }
    g_W[idx] = packh2(x0, x1);
}

// ---------------- layer1 input pack: concat(F3,P) -> g_A1p --------------------
__global__ __launch_bounds__(256) void prep_a1_kernel(const float* __restrict__ F3,
                                                      const float* __restrict__ P) {
    size_t idx = (size_t)blockIdx.x * 256 + threadIdx.x;
    if (idx >= (size_t)MDIM * KP_1) return;
    int m = (int)(idx / KP_1), kp = (int)(idx % KP_1);
    int c = 2 * kp;
    float x0 = 0.f, x1 = 0.f;
    if (c < 3)        x0 = F3[m * 3 + c];
    else if (c < 966) x0 = P[(size_t)m * 963 + (c - 3)];
    int c1 = c + 1;
    if (c1 < 3)        x1 = F3[m * 3 + c1];
    else if (c1 < 966) x1 = P[(size_t)m * 963 + (c1 - 3)];
    g_A1p[idx] = packh2(x0, x1);
}

// ---------------- fp16 tensor-core GEMM (R9 mainloop) -------------------------
// block tile 256x64, warp tile 64x32, 4-stage cp.async pipeline, wait_group 2
// epilogue: cols < 64 scaled + -> g_Sside; cols >= 64 -> g_Ssup
// asel: 0 -> g_Xp (akp=96), 1 -> g_Fp (96), 2 -> g_A1p (488)
__global__ __launch_bounds__(256, 2) void gemm_f16_kernel(int asel, int woff, int NT) {
    __shared__ uint32_t As[4][256][8];      // swizzled: col ^= ((row>>2)&1)*4
    __shared__ uint32_t Bs[4][8][72];       // [stage][kpair][n], padded

    const uint32_t* Ap; int akp;
    if (asel == 0)      { Ap = g_Xp;  akp = KP_H; }
    else if (asel == 1) { Ap = g_Fp;  akp = KP_H; }
    else                { Ap = g_A1p; akp = KP_1; }

    int t = threadIdx.x, lane = t & 31, warp = t >> 5;
    int wm = (warp >> 1) * 64, wn = (warp & 1) * 32;
    int g = lane >> 2, t4 = lane & 3;
    int rowBase = blockIdx.y * 256, colBase = blockIdx.x * 64;

    float acc[4][4][4];
    #pragma unroll
    for (int mt = 0; mt < 4; mt++)
        #pragma unroll
        for (int nt = 0; nt < 4; nt++)
            #pragma unroll
            for (int i = 0; i < 4; i++) acc[mt][nt][i] = 0.f;

    int b_kp = t >> 4, b_n4 = (t & 15) * 4;
    int lm_row = lane & 15;
    int lm_k4  = (lane >> 4) * 4;

    auto load_stage = [&](int kt) {
        int s = kt & 3;
        int k0p = kt * 8;
        int ok = (kt < NT) ? 16 : 0;
        #pragma unroll
        for (int i = 0; i < 2; i++) {
            int c = t + i * 256;
            int row = c >> 1, half = c & 1;
            int gm = rowBase + row;
            int dcol = (half * 4) ^ (((row >> 2) & 1) * 4);
            cpa16(smem_u32(&As[s][row][dcol]),
                  Ap + (size_t)gm * akp + k0p + half * 4,
                  (gm < MDIM) ? ok : 0);
        }
        if (t < 128)
            cpa16(smem_u32(&Bs[s][b_kp][b_n4]),
                  g_W + (size_t)(woff + k0p + b_kp) * HH + colBase + b_n4,
                  ok);
        asm volatile("cp.async.commit_group;\n");
    };

    load_stage(0);
    load_stage(1);
    load_stage(2);

    for (int kt = 0; kt < NT; kt++) {
        asm volatile("cp.async.wait_group %0;\n" :: "n"(2));
        __syncthreads();

        int s = kt & 3;
        uint32_t a[4][4];
        #pragma unroll
        for (int mt = 0; mt < 4; mt++) {
            int row = wm + mt * 16 + lm_row;
            int col = lm_k4 ^ (((row >> 2) & 1) * 4);
            ldsm4(a[mt], smem_u32(&As[s][row][col]));
        }
        #pragma unroll
        for (int nt = 0; nt < 4; nt++) {
            int cn = wn + nt * 8 + g;
            uint32_t b[2] = { Bs[s][t4][cn], Bs[s][t4 + 4][cn] };
            #pragma unroll
            for (int mt = 0; mt < 4; mt++)
                mma16(acc[mt][nt], a[mt], b);
        }
        __syncthreads();
        load_stage(kt + 3);
    }

    // ---- epilogue: pack half2; side (cols<64) scaled -> g_Sside; else g_Ssup ----
    #pragma unroll
    for (int mt = 0; mt < 4; mt++) {
        int gm0 = rowBase + wm + mt * 16 + g;
        #pragma unroll
        for (int nt = 0; nt < 4; nt++) {
            int gc = colBase + wn + nt * 8 + t4 * 2;
            int cp = gc >> 1;
            bool side = (gc < 64);
            if (gm0 < MDIM) {
                if (side) {
                    float sc = g_invdeg[gm0 % VV];
                    g_Sside[(size_t)gm0 * 32 + cp] = packh2(acc[mt][nt][0] * sc, acc[mt][nt][1] * sc);
                } else {
                    g_Ssup[(size_t)gm0 * 64 + cp - 32] = packh2(acc[mt][nt][0], acc[mt][nt][1]);
                }
            }
            int gm1 = gm0 + 8;
            if (gm1 < MDIM) {
                if (side) {
                    float sc = g_invdeg[gm1 % VV];
                    g_Sside[(size_t)gm1 * 32 + cp] = packh2(acc[mt][nt][2] * sc, acc[mt][nt][3] * sc);
                } else {
                    g_Ssup[(size_t)gm1 * 64 + cp - 32] = packh2(acc[mt][nt][2], acc[mt][nt][3]);
                }
            }
        }
    }
}

// ---------------- fused combine + BN stats + apply (per vertex) --------------
// mode 0: X = relu(bn)                (write g_Xp plane)
// mode 1: F = (concat_first192+y)/2   (write g_Fp)
// mode 2: F = (F + y)/2               (g_Fp read+write)
// mode 3: mode 2 + write dout (fp32 value before fp16 rounding)
__global__ __launch_bounds__(256) void post_kernel(
    const float* __restrict__ bias,
    const float* __restrict__ gam, const float* __restrict__ bet,
    const float* __restrict__ F3, const float* __restrict__ P,
    float* __restrict__ dout, int mode)
{
    int v = blockIdx.x, t = threadIdx.x;
    __shared__ float ybuf[BB * HH];
    __shared__ float sbias[HH];
    __shared__ int   s_nbr[8];
    __shared__ float s_w[8];
    __shared__ int   s_cnt;
    __shared__ float redS[8], redQ[8];
    __shared__ float s_mean, s_istd;

    if (t < 8) { s_nbr[t] = g_nbr[v * 8 + t]; s_w[t] = g_w[v * 8 + t]; }
    if (t == 0) s_cnt = g_cnt[v];
    if (t < HH) sbias[t] = bias[t];
    __syncthreads();
    int cnt = s_cnt;

    float s = 0.f, ss = 0.f;
    #pragma unroll
    for (int it = 0; it < 12; it++) {
        int i = t + it * 256;
        int b = i / KP_H, cp = i - b * KP_H;
        int c = 2 * cp;
        float y0, y1;
        if (cp < 64) {
            float2 p = unpackh2(g_Ssup[((size_t)(b * VV + v)) * 64 + cp]);
            y0 = p.x; y1 = p.y;
        } else {
            int dp = cp - 64;
            y0 = 0.f; y1 = 0.f;
            for (int j = 0; j < cnt; j++) {
                float2 p = unpackh2(g_Sside[((size_t)(b * VV + s_nbr[j])) * 32 + dp]);
                y0 += s_w[j] * p.x; y1 += s_w[j] * p.y;
            }
        }
        y0 += sbias[c]; y1 += sbias[c + 1];
        ybuf[2 * i] = y0; ybuf[2 * i + 1] = y1;
        s += y0 + y1; ss += y0 * y0 + y1 * y1;
    }
    #pragma unroll
    for (int o = 16; o > 0; o >>= 1) {
        s  += __shfl_down_sync(0xffffffffu, s, o);
        ss += __shfl_down_sync(0xffffffffu, ss, o);
    }
    int lane = t & 31, warp = t >> 5;
    if (lane == 0) { redS[warp] = s; redQ[warp] = ss; }
    __syncthreads();
    if (t == 0) {
        float S = 0.f, Q = 0.f;
        #pragma unroll
        for (int w = 0; w < 8; w++) { S += redS[w]; Q += redQ[w]; }
        float n = (float)(BB * HH);
        float mu = S / n;
        s_mean = mu;
        s_istd = rsqrtf(Q / n - mu * mu + 1e-5f);
    }
    __syncthreads();

    float gv = gam[v], bv = bet[v], mu = s_mean, istd = s_istd;
    #pragma unroll
    for (int it = 0; it < 12; it++) {
        int i = t + it * 256;
        int b = i / KP_H, cp = i - b * KP_H;
        int c = 2 * cp;
        int m = b * VV + v;
        float y0 = fmaxf(gv * (ybuf[2 * i]     - mu) * istd + bv, 0.f);
        float y1 = fmaxf(gv * (ybuf[2 * i + 1] - mu) * istd + bv, 0.f);
        size_t pidx = (size_t)m * KP_H + cp;
        if (mode == 0) {
            g_Xp[pidx] = packh2(y0, y1);
        } else {
            float r0, r1;
            if (mode == 1) {
                float b0 = (c < 3)     ? F3[m * 3 + c]     : P[(size_t)m * 963 + (c - 3)];
                float b1 = (c + 1 < 3) ? F3[m * 3 + c + 1] : P[(size_t)m * 963 + (c - 2)];
                r0 = (b0 + y0) * 0.5f; r1 = (b1 + y1) * 0.5f;
            } else {
                float2 f = unpackh2(g_Fp[pidx]);
                r0 = (f.x + y0) * 0.5f; r1 = (f.y + y1) * 0.5f;
            }
            g_Fp[pidx] = packh2(r0, r1);
            if (mode == 3)
                *reinterpret_cast<float2*>(&dout[(size_t)m * HH + c]) = make_float2(r0, r1);
        }
    }
}

// ---------------- head GEMM: S3 = feats @ W15, cols<2 pre-scaled -------------
__global__ __launch_bounds__(256) void gemm3_kernel(const float* __restrict__ W15) {
    int warp = (blockIdx.x * blockDim.x + threadIdx.x) >> 5;
    int lane = threadIdx.x & 31;
    if (warp >= MDIM) return;
    const uint32_t* row = g_Fp + (size_t)warp * KP_H;
    float a0 = 0.f, a1 = 0.f, a2 = 0.f;
    for (int kp = lane; kp < KP_H; kp += 32) {
        float2 f = unpackh2(row[kp]);
        int k = 2 * kp;
        a0 = fmaf(f.x, W15[k * 3 + 0], a0);
        a1 = fmaf(f.x, W15[k * 3 + 1], a1);
        a2 = fmaf(f.x, W15[k * 3 + 2], a2);
        a0 = fmaf(f.y, W15[k * 3 + 3], a0);
        a1 = fmaf(f.y, W15[k * 3 + 4], a1);
        a2 = fmaf(f.y, W15[k * 3 + 5], a2);
    }
    #pragma unroll
    for (int o = 16; o > 0; o >>= 1) {
        a0 += __shfl_down_sync(0xffffffffu, a0, o);
        a1 += __shfl_down_sync(0xffffffffu, a1, o);
        a2 += __shfl_down_sync(0xffffffffu, a2, o);
    }
    if (lane == 0) {
        float inv = g_invdeg[warp % VV];
        g_S3[warp * 3 + 0] = a0 * inv;
        g_S3[warp * 3 + 1] = a1 * inv;
        g_S3[warp * 3 + 2] = a2;
    }
}

__global__ __launch_bounds__(256) void coords_kernel(float* __restrict__ dout,
                                                     const float* __restrict__ b15) {
    int m = blockIdx.x * blockDim.x + threadIdx.x;
    if (m >= MDIM) return;
    int v = m % VV, b = m / VV;
    float s0 = 0.f, s1 = 0.f;
    int cnt = g_cnt[v];
    for (int j = 0; j < cnt; j++) {
        int nv = g_nbr[v * 8 + j];
        float w = g_w[v * 8 + j];
        const float* p = g_S3 + (size_t)(b * VV + nv) * 3;
        s0 += w * p[0];
        s1 += w * p[1];
    }
    float* o = dout + (size_t)MDIM * HH + (size_t)m * 3;
    o[0] = g_S3[m * 3 + 2] + b15[0];
    o[1] = s0 + b15[1];
    o[2] = s1 + b15[2];
}

// ---------------- driver ----------------------------------------------------
extern "C" void kernel_launch(void* const* d_in, const int* in_sizes, int n_in,
                              void* d_out, int out_size) {
    const float* features = (const float*)d_in[0];
    const float* pooled   = (const float*)d_in[1];
    const float* adj      = (const float*)d_in[2];
    const float* W1       = (const float*)d_in[3];
    const float* b1       = (const float*)d_in[4];
    const float* Wm       = (const float*)d_in[5];
    const float* bm       = (const float*)d_in[6];
    const float* W15      = (const float*)d_in[7];
    const float* b15      = (const float*)d_in[8];
    const float* gamma    = (const float*)d_in[9];
    const float* beta     = (const float*)d_in[10];
    float* dout = (float*)d_out;

    dim3 ggrid(3, (MDIM + 255) / 256);

    adj_kernel<<<(VV + 7) / 8, 256>>>(adj);
    prep_w_kernel<<<(WROWS * HH + 255) / 256, 256>>>(W1, Wm);
    prep_a1_kernel<<<(int)(((size_t)MDIM * KP_1 + 255) / 256), 256>>>(features, pooled);

    // layer 1
    gemm_f16_kernel<<<ggrid, 256>>>(2, 0, NT_1);
    post_kernel<<<VV, 256>>>(b1, gamma + 0 * VV, beta + 0 * VV, features, pooled, dout, 0);

    // layer 2
    gemm_f16_kernel<<<ggrid, 256>>>(0, KP_1 + 0 * KP_H, NT_H);
    post_kernel<<<VV, 256>>>(bm + 0 * HH, gamma + 1 * VV, beta + 1 * VV, features, pooled, dout, 1);

    for (int i = 0; i < 5; i++) {
        int wa = 2 * i + 1, wb = 2 * i + 2;
        gemm_f16_kernel<<<ggrid, 256>>>(1, KP_1 + wa * KP_H, NT_H);
        post_kernel<<<VV, 256>>>(bm + wa * HH, gamma + (2 * i + 2) * VV, beta + (2 * i + 2) * VV,
                                 features, pooled, dout, 0);
        gemm_f16_kernel<<<ggrid, 256>>>(0, KP_1 + wb * KP_H, NT_H);
        post_kernel<<<VV, 256>>>(bm + wb * HH, gamma + (2 * i + 3) * VV, beta + (2 * i + 3) * VV,
                                 features, pooled, dout, 2);
    }

    // layer 13
    gemm_f16_kernel<<<ggrid, 256>>>(1, KP_1 + 11 * KP_H, NT_H);
    post_kernel<<<VV, 256>>>(bm + 11 * HH, gamma + 12 * VV, beta + 12 * VV, features, pooled, dout, 3);

    gemm3_kernel<<<(MDIM * 32 + 255) / 256, 256>>>(W15);
    coords_kernel<<<(MDIM + 255) / 256, 256>>>(dout, b15);
}